// round 5
// baseline (speedup 1.0000x reference)
#include <cuda_runtime.h>
#include <cstdint>

// Problem constants
#define BQ   8
#define HQ   16
#define NQ   8192
#define HD   64
#define NJ   20
#define TILE 256         // query positions per block
#define HALO 128         // largest offset served from smem
#define HROWS (TILE + HALO)   // 384 rows in halo
#define PPG  4           // positions per 8-lane group
#define NE   35          // distinct smem band rows per quad

static __device__ __forceinline__ unsigned long long pk2(float lo, float hi) {
    unsigned long long r;
    asm("mov.b64 %0, {%1,%2};" : "=l"(r) : "f"(lo), "f"(hi));
    return r;
}
static __device__ __forceinline__ unsigned long long f2fma(unsigned long long a, unsigned long long b, unsigned long long c) {
    unsigned long long r;
    asm("fma.rn.f32x2 %0, %1, %2, %3;" : "=l"(r) : "l"(a), "l"(b), "l"(c));
    return r;
}
static __device__ __forceinline__ unsigned long long f2mul(unsigned long long a, unsigned long long b) {
    unsigned long long r;
    asm("mul.rn.f32x2 %0, %1, %2;" : "=l"(r) : "l"(a), "l"(b));
    return r;
}
static __device__ __forceinline__ float f2hadd(unsigned long long a) {
    float lo, hi;
    asm("mov.b64 {%0,%1}, %2;" : "=f"(lo), "=f"(hi) : "l"(a));
    return lo + hi;
}
static __device__ __forceinline__ float dot8(const ulonglong2& A0, const ulonglong2& A1,
                                             const ulonglong2& B0, const ulonglong2& B1) {
    unsigned long long t =
        f2fma(A0.x, B0.x, f2fma(A0.y, B0.y, f2fma(A1.x, B1.x, f2fma(A1.y, B1.y, 0ull))));
    return f2hadd(t);
}

// offsets
__device__ __forceinline__ constexpr int offs(int j) {
    constexpr int O[NJ] = {1,2,3,4,5,6,7,8,9,11,13,15,16,23,32,64,128,256,512,1024};
    return O[j];
}
// smem band row displacements e (row = n - e serves position n+p when e+p is an offset)
__device__ __forceinline__ constexpr int erow(int i) {
    constexpr int E[NE] = {-2,-1,0,1,2,3,4,5,6,7,8,9,10,11,12,13,14,15,16,
                           20,21,22,23, 29,30,31,32, 61,62,63,64, 125,126,127,128};
    return E[i];
}
// offset -> j index (smem-range offsets only), -1 if not an offset
__device__ __forceinline__ constexpr int jof(int d) {
    switch (d) {
        case 1: return 0;  case 2: return 1;  case 3: return 2;  case 4: return 3;
        case 5: return 4;  case 6: return 5;  case 7: return 6;  case 8: return 7;
        case 9: return 8;  case 11: return 9; case 13: return 10; case 15: return 11;
        case 16: return 12; case 23: return 13; case 32: return 14; case 64: return 15;
        case 128: return 16;
        default: return -1;
    }
}

#define SK_FLOATS  (HROWS * HD)      // 24576
#define SSE_FLOATS (NJ * HD)         // 1280
#define SMEM_FLOATS (2 * SK_FLOATS + SSE_FLOATS + 32)
#define SMEM_BYTES  (SMEM_FLOATS * 4)

__global__ void __launch_bounds__(512, 1)
dsqg_attn_kernel(const float* __restrict__ q,
                 const float* __restrict__ k,
                 const float* __restrict__ v,
                 const float* __restrict__ pb,   // [NJ, HQ]
                 const float* __restrict__ se,   // [NJ, HD]
                 float* __restrict__ out)
{
    extern __shared__ float sm[];
    float* sk  = sm;                       // [HROWS][HD]
    float* sv  = sm + SK_FLOATS;           // [HROWS][HD]
    float* sse = sm + 2 * SK_FLOATS;       // [NJ][HD]
    float* spb = sse + SSE_FLOATS;         // [NJ]

    const int bh   = blockIdx.y;
    const int h    = bh & (HQ - 1);
    const int n0   = blockIdx.x * TILE;
    const int base = bh * (NQ * HD);
    const int tid  = threadIdx.x;

    // ---- cooperative fills (coalesced float4) ----
    {
        const int total4 = SK_FLOATS / 4;  // 6144
        const int e0 = (n0 - HALO) * HD;
        #pragma unroll 2
        for (int i = tid; i < total4; i += 512) {
            int ge = e0 + i * 4;
            float4 kv = make_float4(0.f, 0.f, 0.f, 0.f);
            float4 vv = kv;
            if (ge >= 0) {
                kv = *(const float4*)(k + base + ge);
                vv = *(const float4*)(v + base + ge);
            }
            ((float4*)sk)[i] = kv;
            ((float4*)sv)[i] = vv;
        }
        for (int i = tid; i < SSE_FLOATS / 4; i += 512)
            ((float4*)sse)[i] = ((const float4*)se)[i];
        if (tid < NJ) spb[tid] = pb[tid * HQ + h];
    }
    __syncthreads();

    // 8-lane groups; group g handles 4 consecutive positions n..n+3.
    // lane l owns channels [4l..4l+3] and [32+4l..32+4l+3] (conflict-free 16B).
    const int g  = tid >> 3;       // 0..63
    const int l  = tid & 7;
    const int c0 = l * 4;
    const int c1 = 32 + l * 4;
    const int n  = n0 + g * PPG;
    const int liBase = g * PPG + HALO;     // local halo row of position n
    const float NEG_INF = __int_as_float(0xff800000);

    // Q for 4 positions
    ulonglong2 Q0[PPG], Q1[PPG];
    #pragma unroll
    for (int p = 0; p < PPG; ++p) {
        const float* qr = q + base + (n + p) * HD;
        Q0[p] = *(const ulonglong2*)(qr + c0);
        Q1[p] = *(const ulonglong2*)(qr + c1);
    }

    float s[PPG][NJ];

    // ---- pass 1a: q . se_j (broadcast smem reads, cheap) ----
    #pragma unroll
    for (int j = 0; j < NJ; ++j) {
        const float* ser = sse + j * HD;
        const ulonglong2 S0 = *(const ulonglong2*)(ser + c0);
        const ulonglong2 S1 = *(const ulonglong2*)(ser + c1);
        #pragma unroll
        for (int p = 0; p < PPG; ++p)
            s[p][j] = dot8(Q0[p], Q1[p], S0, S1);
    }

    // ---- pass 1b: smem band rows, each row reused by up to 4 positions ----
    #pragma unroll
    for (int ei = 0; ei < NE; ++ei) {
        const int e = erow(ei);
        const float* kr = sk + (liBase - e) * HD;
        const ulonglong2 K0 = *(const ulonglong2*)(kr + c0);
        const ulonglong2 K1 = *(const ulonglong2*)(kr + c1);
        #pragma unroll
        for (int p = 0; p < PPG; ++p) {
            const int j = jof(e + p);
            if (j >= 0)
                s[p][j] += dot8(Q0[p], Q1[p], K0, K1);
        }
    }

    // ---- pass 1c: far offsets from global (L2) ----
    #pragma unroll
    for (int jf = 0; jf < 3; ++jf) {
        const int d = (jf == 0) ? 256 : ((jf == 1) ? 512 : 1024);
        const int j = 17 + jf;
        #pragma unroll
        for (int p = 0; p < PPG; ++p) {
            if (n + p >= d) {
                const float* kr = k + base + (n + p - d) * HD;
                const ulonglong2 K0 = *(const ulonglong2*)(kr + c0);
                const ulonglong2 K1 = *(const ulonglong2*)(kr + c1);
                s[p][j] += dot8(Q0[p], Q1[p], K0, K1);
            }
        }
    }

    // ---- finalize scores: 8-lane reduce, mask, softmax (weights left unnormalized) ----
    float inv[PPG];
    #pragma unroll
    for (int p = 0; p < PPG; ++p) {
        #pragma unroll
        for (int j = 0; j < NJ; ++j) {
            float t = s[p][j];
            t += __shfl_xor_sync(0xffffffffu, t, 1);
            t += __shfl_xor_sync(0xffffffffu, t, 2);
            t += __shfl_xor_sync(0xffffffffu, t, 4);
            s[p][j] = ((n + p) >= offs(j)) ? fmaf(t, 0.125f, spb[j]) : NEG_INF;
        }
        float m = s[p][0];
        #pragma unroll
        for (int j = 1; j < NJ; ++j) m = fmaxf(m, s[p][j]);
        if ((n + p) == 0) m = 0.f;          // all masked -> exp(-inf)=0
        float den = 0.f;
        #pragma unroll
        for (int j = 0; j < NJ; ++j) {
            s[p][j] = __expf(s[p][j] - m);
            den += s[p][j];
        }
        inv[p] = __frcp_rn(fmaxf(den, 1e-30f));
    }

    // ---- pass 2: weighted V accumulation with the same row reuse ----
    ulonglong2 A0[PPG], A1[PPG];
    #pragma unroll
    for (int p = 0; p < PPG; ++p) {
        A0[p].x = A0[p].y = A1[p].x = A1[p].y = 0ull;
    }

    #pragma unroll
    for (int ei = 0; ei < NE; ++ei) {
        const int e = erow(ei);
        const float* vr = sv + (liBase - e) * HD;
        const ulonglong2 V0 = *(const ulonglong2*)(vr + c0);
        const ulonglong2 V1 = *(const ulonglong2*)(vr + c1);
        #pragma unroll
        for (int p = 0; p < PPG; ++p) {
            const int j = jof(e + p);
            if (j >= 0) {
                const float w = s[p][j];
                const unsigned long long w2 = pk2(w, w);
                A0[p].x = f2fma(w2, V0.x, A0[p].x);
                A0[p].y = f2fma(w2, V0.y, A0[p].y);
                A1[p].x = f2fma(w2, V1.x, A1[p].x);
                A1[p].y = f2fma(w2, V1.y, A1[p].y);
            }
        }
    }

    #pragma unroll
    for (int jf = 0; jf < 3; ++jf) {
        const int d = (jf == 0) ? 256 : ((jf == 1) ? 512 : 1024);
        const int j = 17 + jf;
        #pragma unroll
        for (int p = 0; p < PPG; ++p) {
            if (n + p >= d) {
                const float* vr = v + base + (n + p - d) * HD;
                const ulonglong2 V0 = *(const ulonglong2*)(vr + c0);
                const ulonglong2 V1 = *(const ulonglong2*)(vr + c1);
                const float w = s[p][j];
                const unsigned long long w2 = pk2(w, w);
                A0[p].x = f2fma(w2, V0.x, A0[p].x);
                A0[p].y = f2fma(w2, V0.y, A0[p].y);
                A1[p].x = f2fma(w2, V1.x, A1[p].x);
                A1[p].y = f2fma(w2, V1.y, A1[p].y);
            }
        }
    }

    // ---- normalize + store ----
    #pragma unroll
    for (int p = 0; p < PPG; ++p) {
        const unsigned long long iv2 = pk2(inv[p], inv[p]);
        ulonglong2 R0, R1;
        R0.x = f2mul(A0[p].x, iv2);
        R0.y = f2mul(A0[p].y, iv2);
        R1.x = f2mul(A1[p].x, iv2);
        R1.y = f2mul(A1[p].y, iv2);
        float* outr = out + base + (n + p) * HD;
        *(ulonglong2*)(outr + c0) = R0;
        *(ulonglong2*)(outr + c1) = R1;
    }
}

extern "C" void kernel_launch(void* const* d_in, const int* in_sizes, int n_in,
                              void* d_out, int out_size)
{
    const float* q  = (const float*)d_in[0];
    const float* k  = (const float*)d_in[1];
    const float* v  = (const float*)d_in[2];
    const float* pb = (const float*)d_in[3];
    const float* se = (const float*)d_in[4];
    float* out = (float*)d_out;

    cudaFuncSetAttribute(dsqg_attn_kernel,
                         cudaFuncAttributeMaxDynamicSharedMemorySize, SMEM_BYTES);

    dim3 grid(NQ / TILE, BQ * HQ);
    dsqg_attn_kernel<<<grid, 512, SMEM_BYTES>>>(q, k, v, pb, se, out);
}

// round 6
// speedup vs baseline: 1.0432x; 1.0432x over previous
#include <cuda_runtime.h>
#include <cstdint>

// Problem constants
#define BQ   8
#define HQ   16
#define NQ   8192
#define HD   64
#define NJ   20
#define TILE 256         // query positions per main block
#define HALO 128
#define HROWS (TILE + HALO)   // 384
#define PPG  2           // positions per 8-lane group
#define NE   25          // distinct smem band rows per pair

// 84MB scratch for precomputed (q.se_j)*sc + pb[j,h]
__device__ float g_pre[BQ * HQ * NQ * NJ];

static __device__ __forceinline__ unsigned long long pk2(float lo, float hi) {
    unsigned long long r;
    asm("mov.b64 %0, {%1,%2};" : "=l"(r) : "f"(lo), "f"(hi));
    return r;
}
static __device__ __forceinline__ unsigned long long f2fma(unsigned long long a, unsigned long long b, unsigned long long c) {
    unsigned long long r;
    asm("fma.rn.f32x2 %0, %1, %2, %3;" : "=l"(r) : "l"(a), "l"(b), "l"(c));
    return r;
}
static __device__ __forceinline__ unsigned long long f2mul(unsigned long long a, unsigned long long b) {
    unsigned long long r;
    asm("mul.rn.f32x2 %0, %1, %2;" : "=l"(r) : "l"(a), "l"(b));
    return r;
}
static __device__ __forceinline__ float f2hadd(unsigned long long a) {
    float lo, hi;
    asm("mov.b64 {%0,%1}, %2;" : "=f"(lo), "=f"(hi) : "l"(a));
    return lo + hi;
}
static __device__ __forceinline__ float dot8(const ulonglong2& A0, const ulonglong2& A1,
                                             const ulonglong2& B0, const ulonglong2& B1) {
    unsigned long long t =
        f2fma(A0.x, B0.x, f2fma(A0.y, B0.y, f2fma(A1.x, B1.x, f2fma(A1.y, B1.y, 0ull))));
    return f2hadd(t);
}
static __device__ __forceinline__ float bfly8(float p) {
    p += __shfl_xor_sync(0xffffffffu, p, 1);
    p += __shfl_xor_sync(0xffffffffu, p, 2);
    p += __shfl_xor_sync(0xffffffffu, p, 4);
    return p;
}

__device__ __forceinline__ constexpr int offs(int j) {
    constexpr int O[NJ] = {1,2,3,4,5,6,7,8,9,11,13,15,16,23,32,64,128,256,512,1024};
    return O[j];
}
// band row displacements for a pair: e such that e+p is a smem offset for p in {0,1}
__device__ __forceinline__ constexpr int erow(int i) {
    constexpr int E[NE] = {0,1,2,3,4,5,6,7,8,9,10,11,12,13,14,15,16,
                           22,23, 31,32, 63,64, 127,128};
    return E[i];
}
__device__ __forceinline__ constexpr int jof(int d) {
    switch (d) {
        case 1: return 0;  case 2: return 1;  case 3: return 2;  case 4: return 3;
        case 5: return 4;  case 6: return 5;  case 7: return 6;  case 8: return 7;
        case 9: return 8;  case 11: return 9; case 13: return 10; case 15: return 11;
        case 16: return 12; case 23: return 13; case 32: return 14; case 64: return 15;
        case 128: return 16;
        default: return -1;
    }
}

#define SK_FLOATS  (HROWS * HD)      // 24576
#define SMEM_FLOATS (2 * SK_FLOATS)
#define SMEM_BYTES  (SMEM_FLOATS * 4)   // 196608

// ---------------- Kernel A: pre[bh][n][j] = (q . se_j)*sc + pb[j,h] ----------------
__global__ void __launch_bounds__(256)
dsqg_pre_kernel(const float* __restrict__ q,
                const float* __restrict__ pb,   // [NJ, HQ]
                const float* __restrict__ se)   // [NJ, HD]
{
    __shared__ float sse[NJ * HD];
    __shared__ float spb[NJ];

    const int bh   = blockIdx.y;
    const int h    = bh & (HQ - 1);
    const int n0   = blockIdx.x * 32;
    const int base = bh * (NQ * HD);
    const int tid  = threadIdx.x;

    for (int i = tid; i < (NJ * HD) / 4; i += 256)
        ((float4*)sse)[i] = ((const float4*)se)[i];
    if (tid < NJ) spb[tid] = pb[tid * HQ + h];
    __syncthreads();

    const int g  = tid >> 3;
    const int l  = tid & 7;
    const int c0 = l * 4;
    const int c1 = 32 + l * 4;
    const int n  = n0 + g;

    const float* qr = q + base + n * HD;
    const ulonglong2 Q0 = *(const ulonglong2*)(qr + c0);
    const ulonglong2 Q1 = *(const ulonglong2*)(qr + c1);

    float s[NJ];
    #pragma unroll
    for (int j = 0; j < NJ; ++j) {
        const float* ser = sse + j * HD;
        const ulonglong2 S0 = *(const ulonglong2*)(ser + c0);
        const ulonglong2 S1 = *(const ulonglong2*)(ser + c1);
        float t = bfly8(dot8(Q0, Q1, S0, S1));
        s[j] = fmaf(t, 0.125f, spb[j]);
    }

    // lanes 0..4 write contiguous float4s (compile-time indexed pack)
    float4 f;
    switch (l) {
        case 0: f = make_float4(s[0],  s[1],  s[2],  s[3]);  break;
        case 1: f = make_float4(s[4],  s[5],  s[6],  s[7]);  break;
        case 2: f = make_float4(s[8],  s[9],  s[10], s[11]); break;
        case 3: f = make_float4(s[12], s[13], s[14], s[15]); break;
        case 4: f = make_float4(s[16], s[17], s[18], s[19]); break;
        default: f = make_float4(0.f, 0.f, 0.f, 0.f); break;
    }
    if (l < 5)
        *(float4*)(g_pre + (bh * NQ + n) * NJ + l * 4) = f;
}

// ---------------- Kernel B: main attention ----------------
__global__ void __launch_bounds__(1024, 1)
dsqg_attn_kernel(const float* __restrict__ q,
                 const float* __restrict__ k,
                 const float* __restrict__ v,
                 float* __restrict__ out)
{
    extern __shared__ float sm[];
    float* sk = sm;                  // [HROWS][HD]
    float* sv = sm + SK_FLOATS;      // [HROWS][HD]

    const int bh   = blockIdx.y;
    const int n0   = blockIdx.x * TILE;
    const int base = bh * (NQ * HD);
    const int tid  = threadIdx.x;

    // ---- cooperative fills ----
    {
        const int total4 = SK_FLOATS / 4;   // 6144 per array
        const int e0 = (n0 - HALO) * HD;
        #pragma unroll 2
        for (int i = tid; i < total4; i += 1024) {
            int ge = e0 + i * 4;
            float4 kv = make_float4(0.f, 0.f, 0.f, 0.f);
            float4 vv = kv;
            if (ge >= 0) {
                kv = *(const float4*)(k + base + ge);
                vv = *(const float4*)(v + base + ge);
            }
            ((float4*)sk)[i] = kv;
            ((float4*)sv)[i] = vv;
        }
    }
    __syncthreads();

    const int g  = tid >> 3;        // 0..127
    const int l  = tid & 7;
    const int c0 = l * 4;
    const int c1 = 32 + l * 4;
    const int n  = n0 + g * PPG;
    const int liBase = g * PPG + HALO;   // halo row of position n
    const float NEG_INF = __int_as_float(0xff800000);

    // Q for 2 positions
    ulonglong2 Q0[PPG], Q1[PPG];
    #pragma unroll
    for (int p = 0; p < PPG; ++p) {
        const float* qr = q + base + (n + p) * HD;
        Q0[p] = *(const ulonglong2*)(qr + c0);
        Q1[p] = *(const ulonglong2*)(qr + c1);
    }

    // init scores from precomputed (q.se)*sc + pb  (broadcast LDG.128)
    float s[PPG][NJ];
    #pragma unroll
    for (int p = 0; p < PPG; ++p) {
        const float4* pp = (const float4*)(g_pre + (bh * NQ + n + p) * NJ);
        #pragma unroll
        for (int t4 = 0; t4 < 5; ++t4) {
            float4 f = pp[t4];
            s[p][t4 * 4 + 0] = f.x;
            s[p][t4 * 4 + 1] = f.y;
            s[p][t4 * 4 + 2] = f.z;
            s[p][t4 * 4 + 3] = f.w;
        }
    }

    // ---- pass 1: band rows from smem, each k row shared by the pair ----
    #pragma unroll
    for (int ei = 0; ei < NE; ++ei) {
        const int e = erow(ei);
        const float* kr = sk + (liBase - e) * HD;
        const ulonglong2 K0 = *(const ulonglong2*)(kr + c0);
        const ulonglong2 K1 = *(const ulonglong2*)(kr + c1);
        #pragma unroll
        for (int p = 0; p < PPG; ++p) {
            const int j = jof(e + p);      // compile-time
            if (j >= 0) {
                float t = bfly8(dot8(Q0[p], Q1[p], K0, K1));
                s[p][j] = ((n + p) >= (e + p)) ? fmaf(t, 0.125f, s[p][j]) : NEG_INF;
            }
        }
    }

    // ---- far offsets from global (clamped loads, uniform shuffles) ----
    #pragma unroll
    for (int jf = 0; jf < 3; ++jf) {
        const int d = (jf == 0) ? 256 : ((jf == 1) ? 512 : 1024);
        const int j = 17 + jf;
        #pragma unroll
        for (int p = 0; p < PPG; ++p) {
            const bool valid = (n + p) >= d;
            const int idx = valid ? (n + p - d) : 0;
            const float* kr = k + base + idx * HD;
            const ulonglong2 K0 = *(const ulonglong2*)(kr + c0);
            const ulonglong2 K1 = *(const ulonglong2*)(kr + c1);
            float t = bfly8(dot8(Q0[p], Q1[p], K0, K1));
            s[p][j] = valid ? fmaf(t, 0.125f, s[p][j]) : NEG_INF;
        }
    }

    // ---- softmax (unnormalized weights; normalize at store) ----
    float inv[PPG];
    #pragma unroll
    for (int p = 0; p < PPG; ++p) {
        float m = s[p][0];
        #pragma unroll
        for (int j = 1; j < NJ; ++j) m = fmaxf(m, s[p][j]);
        if ((n + p) == 0) m = 0.f;
        float den = 0.f;
        #pragma unroll
        for (int j = 0; j < NJ; ++j) {
            s[p][j] = __expf(s[p][j] - m);
            den += s[p][j];
        }
        inv[p] = __frcp_rn(fmaxf(den, 1e-30f));
    }

    // ---- pass 2: weighted V with the same row reuse ----
    ulonglong2 A0[PPG], A1[PPG];
    #pragma unroll
    for (int p = 0; p < PPG; ++p) {
        A0[p].x = A0[p].y = A1[p].x = A1[p].y = 0ull;
    }

    #pragma unroll
    for (int ei = 0; ei < NE; ++ei) {
        const int e = erow(ei);
        const float* vr = sv + (liBase - e) * HD;
        const ulonglong2 V0 = *(const ulonglong2*)(vr + c0);
        const ulonglong2 V1 = *(const ulonglong2*)(vr + c1);
        #pragma unroll
        for (int p = 0; p < PPG; ++p) {
            const int j = jof(e + p);
            if (j >= 0) {
                const float w = s[p][j];   // masked positions carry w=0
                const unsigned long long w2 = pk2(w, w);
                A0[p].x = f2fma(w2, V0.x, A0[p].x);
                A0[p].y = f2fma(w2, V0.y, A0[p].y);
                A1[p].x = f2fma(w2, V1.x, A1[p].x);
                A1[p].y = f2fma(w2, V1.y, A1[p].y);
            }
        }
    }

    #pragma unroll
    for (int jf = 0; jf < 3; ++jf) {
        const int d = (jf == 0) ? 256 : ((jf == 1) ? 512 : 1024);
        const int j = 17 + jf;
        #pragma unroll
        for (int p = 0; p < PPG; ++p) {
            const bool valid = (n + p) >= d;
            const int idx = valid ? (n + p - d) : 0;
            const float* vr = v + base + idx * HD;
            const ulonglong2 V0 = *(const ulonglong2*)(vr + c0);
            const ulonglong2 V1 = *(const ulonglong2*)(vr + c1);
            const float w = valid ? s[p][j] : 0.f;
            const unsigned long long w2 = pk2(w, w);
            A0[p].x = f2fma(w2, V0.x, A0[p].x);
            A0[p].y = f2fma(w2, V0.y, A0[p].y);
            A1[p].x = f2fma(w2, V1.x, A1[p].x);
            A1[p].y = f2fma(w2, V1.y, A1[p].y);
        }
    }

    // ---- normalize + store ----
    #pragma unroll
    for (int p = 0; p < PPG; ++p) {
        const unsigned long long iv2 = pk2(inv[p], inv[p]);
        ulonglong2 R0, R1;
        R0.x = f2mul(A0[p].x, iv2);
        R0.y = f2mul(A0[p].y, iv2);
        R1.x = f2mul(A1[p].x, iv2);
        R1.y = f2mul(A1[p].y, iv2);
        float* outr = out + base + (n + p) * HD;
        *(ulonglong2*)(outr + c0) = R0;
        *(ulonglong2*)(outr + c1) = R1;
    }
}

extern "C" void kernel_launch(void* const* d_in, const int* in_sizes, int n_in,
                              void* d_out, int out_size)
{
    const float* q  = (const float*)d_in[0];
    const float* k  = (const float*)d_in[1];
    const float* v  = (const float*)d_in[2];
    const float* pb = (const float*)d_in[3];
    const float* se = (const float*)d_in[4];
    float* out = (float*)d_out;

    cudaFuncSetAttribute(dsqg_attn_kernel,
                         cudaFuncAttributeMaxDynamicSharedMemorySize, SMEM_BYTES);

    dim3 gridA(NQ / 32, BQ * HQ);
    dsqg_pre_kernel<<<gridA, 256>>>(q, pb, se);

    dim3 gridB(NQ / TILE, BQ * HQ);
    dsqg_attn_kernel<<<gridB, 1024, SMEM_BYTES>>>(q, k, v, out);
}

// round 7
// speedup vs baseline: 1.1620x; 1.1139x over previous
#include <cuda_runtime.h>
#include <cstdint>

// Problem constants
#define BQ   8
#define HQ   16
#define NQ   8192
#define HD   64
#define NJ   20
#define TILE 256         // query positions per main block
#define HALO 128
#define HROWS (TILE + HALO)   // 384
#define PPG  2           // positions per 8-lane group
#define NE   25          // distinct smem band rows per pair

// 84MB scratch for precomputed (q.se_j)*sc + pb[j,h]
__device__ float g_pre[BQ * HQ * NQ * NJ];

typedef unsigned long long ull;

static __device__ __forceinline__ ull pk2(float lo, float hi) {
    ull r;
    asm("mov.b64 %0, {%1,%2};" : "=l"(r) : "f"(lo), "f"(hi));
    return r;
}
static __device__ __forceinline__ ull f2fma(ull a, ull b, ull c) {
    ull r;
    asm("fma.rn.f32x2 %0, %1, %2, %3;" : "=l"(r) : "l"(a), "l"(b), "l"(c));
    return r;
}
static __device__ __forceinline__ ull f2mul(ull a, ull b) {
    ull r;
    asm("mul.rn.f32x2 %0, %1, %2;" : "=l"(r) : "l"(a), "l"(b));
    return r;
}
static __device__ __forceinline__ float f2hadd(ull a) {
    float lo, hi;
    asm("mov.b64 {%0,%1}, %2;" : "=f"(lo), "=f"(hi) : "l"(a));
    return lo + hi;
}
static __device__ __forceinline__ void unpk2(ull a, float& lo, float& hi) {
    asm("mov.b64 {%0,%1}, %2;" : "=f"(lo), "=f"(hi) : "l"(a));
}
static __device__ __forceinline__ float dot8(const ulonglong2& A0, const ulonglong2& A1,
                                             const ulonglong2& B0, const ulonglong2& B1) {
    ull t =
        f2fma(A0.x, B0.x, f2fma(A0.y, B0.y, f2fma(A1.x, B1.x, f2fma(A1.y, B1.y, 0ull))));
    return f2hadd(t);
}
static __device__ __forceinline__ float bfly8(float p) {
    p += __shfl_xor_sync(0xffffffffu, p, 1);
    p += __shfl_xor_sync(0xffffffffu, p, 2);
    p += __shfl_xor_sync(0xffffffffu, p, 4);
    return p;
}

__device__ __forceinline__ constexpr int offs(int j) {
    constexpr int O[NJ] = {1,2,3,4,5,6,7,8,9,11,13,15,16,23,32,64,128,256,512,1024};
    return O[j];
}
__device__ __forceinline__ constexpr int erow(int i) {
    constexpr int E[NE] = {0,1,2,3,4,5,6,7,8,9,10,11,12,13,14,15,16,
                           22,23, 31,32, 63,64, 127,128};
    return E[i];
}
__device__ __forceinline__ constexpr int jof(int d) {
    switch (d) {
        case 1: return 0;  case 2: return 1;  case 3: return 2;  case 4: return 3;
        case 5: return 4;  case 6: return 5;  case 7: return 6;  case 8: return 7;
        case 9: return 8;  case 11: return 9; case 13: return 10; case 15: return 11;
        case 16: return 12; case 23: return 13; case 32: return 14; case 64: return 15;
        case 128: return 16;
        default: return -1;
    }
}

#define SK_FLOATS  (HROWS * HD)      // 24576
#define SMEM_FLOATS (2 * SK_FLOATS)
#define SMEM_BYTES  (SMEM_FLOATS * 4)   // 196608

// ============ Kernel A: pre[bh][n][j] = (q . se_j)/8 + pb[j,h] =============
// Register-blocked GEMM [N x 64] @ [64 x 20]; no cross-lane reductions.
#define PRE_TILE  1024      // positions per block
#define QP_PAIRS  512
#define QP_STRIDE (QP_PAIRS + 2)   // ull units
#define CCHUNK    16

#define PRE_SMEM_BYTES ((CCHUNK * QP_STRIDE + NJ * HD) * 8 + NJ * 4 + 16)

__global__ void __launch_bounds__(256, 2)
dsqg_pre_kernel(const float* __restrict__ q,
                const float* __restrict__ pb,   // [NJ, HQ]
                const float* __restrict__ se)   // [NJ, HD]
{
    extern __shared__ ull psm[];
    ull* qp  = psm;                         // [CCHUNK][QP_STRIDE]
    ull* se2 = psm + CCHUNK * QP_STRIDE;    // [NJ][HD] splatted (x,x)
    float* spb = (float*)(se2 + NJ * HD);   // [NJ]

    const int bh   = blockIdx.y;
    const int h    = bh & (HQ - 1);
    const int n0   = blockIdx.x * PRE_TILE;
    const int base = bh * (NQ * HD) + n0 * HD;
    const int tid  = threadIdx.x;

    // se2 / spb fill (guarded by first loop-top barrier)
    for (int i = tid; i < NJ * HD; i += 256) {
        float x = se[i];
        se2[i] = pk2(x, x);
    }
    if (tid < NJ) spb[tid] = pb[tid * HQ + h];

    ull acc0[NJ], acc1[NJ];
    #pragma unroll
    for (int j = 0; j < NJ; ++j) { acc0[j] = 0ull; acc1[j] = 0ull; }

    float* qpf = (float*)qp;

    for (int cc = 0; cc < HD; cc += CCHUNK) {
        __syncthreads();   // protect qp from previous compute; covers se2 fill on iter 0
        // fill qp[c][pair] = (q[2p][cc+c], q[2p+1][cc+c]) for c in [0,16)
        #pragma unroll 4
        for (int i = tid; i < (PRE_TILE * CCHUNK) / 4; i += 256) {   // 4096 float4
            const int n  = i >> 2;              // 0..1023
            const int c4 = (i & 3) * 4;         // 0,4,8,12 (relative channel)
            const float4 f = *(const float4*)(q + base + n * HD + cc + c4);
            const int p  = n >> 1;
            const int hh = n & 1;
            qpf[((c4 + 0) * QP_STRIDE + p) * 2 + hh] = f.x;
            qpf[((c4 + 1) * QP_STRIDE + p) * 2 + hh] = f.y;
            qpf[((c4 + 2) * QP_STRIDE + p) * 2 + hh] = f.z;
            qpf[((c4 + 3) * QP_STRIDE + p) * 2 + hh] = f.w;
        }
        __syncthreads();
        // compute: thread owns pairs tid (positions 2t,2t+1) and tid+256 (512+2t, 512+2t+1)
        #pragma unroll
        for (int c = 0; c < CCHUNK; ++c) {
            const ull qv0 = qp[c * QP_STRIDE + tid];
            const ull qv1 = qp[c * QP_STRIDE + tid + 256];
            #pragma unroll
            for (int j = 0; j < NJ; ++j) {
                const ull sev = se2[j * HD + cc + c];
                acc0[j] = f2fma(qv0, sev, acc0[j]);
                acc1[j] = f2fma(qv1, sev, acc1[j]);
            }
        }
    }

    // epilogue: scale + bias, store 2 consecutive positions per acc group
    {
        float slo[NJ], shi[NJ];
        #pragma unroll
        for (int j = 0; j < NJ; ++j) {
            float lo, hi; unpk2(acc0[j], lo, hi);
            slo[j] = fmaf(lo, 0.125f, spb[j]);
            shi[j] = fmaf(hi, 0.125f, spb[j]);
        }
        float* o0 = g_pre + (bh * NQ + n0 + 2 * tid) * NJ;
        #pragma unroll
        for (int t4 = 0; t4 < 5; ++t4)
            ((float4*)o0)[t4] = make_float4(slo[4*t4], slo[4*t4+1], slo[4*t4+2], slo[4*t4+3]);
        float* o1 = o0 + NJ;
        #pragma unroll
        for (int t4 = 0; t4 < 5; ++t4)
            ((float4*)o1)[t4] = make_float4(shi[4*t4], shi[4*t4+1], shi[4*t4+2], shi[4*t4+3]);
    }
    {
        float slo[NJ], shi[NJ];
        #pragma unroll
        for (int j = 0; j < NJ; ++j) {
            float lo, hi; unpk2(acc1[j], lo, hi);
            slo[j] = fmaf(lo, 0.125f, spb[j]);
            shi[j] = fmaf(hi, 0.125f, spb[j]);
        }
        float* o0 = g_pre + (bh * NQ + n0 + 512 + 2 * tid) * NJ;
        #pragma unroll
        for (int t4 = 0; t4 < 5; ++t4)
            ((float4*)o0)[t4] = make_float4(slo[4*t4], slo[4*t4+1], slo[4*t4+2], slo[4*t4+3]);
        float* o1 = o0 + NJ;
        #pragma unroll
        for (int t4 = 0; t4 < 5; ++t4)
            ((float4*)o1)[t4] = make_float4(shi[4*t4], shi[4*t4+1], shi[4*t4+2], shi[4*t4+3]);
    }
}

// ======================= Kernel B: main attention ==========================
__global__ void __launch_bounds__(1024, 1)
dsqg_attn_kernel(const float* __restrict__ q,
                 const float* __restrict__ k,
                 const float* __restrict__ v,
                 float* __restrict__ out)
{
    extern __shared__ float sm[];
    float* sk = sm;                  // [HROWS][HD]
    float* sv = sm + SK_FLOATS;      // [HROWS][HD]

    const int bh   = blockIdx.y;
    const int n0   = blockIdx.x * TILE;
    const int base = bh * (NQ * HD);
    const int tid  = threadIdx.x;

    // ---- cooperative fills ----
    {
        const int total4 = SK_FLOATS / 4;   // 6144 per array
        const int e0 = (n0 - HALO) * HD;
        #pragma unroll 2
        for (int i = tid; i < total4; i += 1024) {
            int ge = e0 + i * 4;
            float4 kv = make_float4(0.f, 0.f, 0.f, 0.f);
            float4 vv = kv;
            if (ge >= 0) {
                kv = *(const float4*)(k + base + ge);
                vv = *(const float4*)(v + base + ge);
            }
            ((float4*)sk)[i] = kv;
            ((float4*)sv)[i] = vv;
        }
    }
    __syncthreads();

    const int g  = tid >> 3;        // 0..127
    const int l  = tid & 7;
    const int c0 = l * 4;
    const int c1 = 32 + l * 4;
    const int n  = n0 + g * PPG;
    const int liBase = g * PPG + HALO;   // halo row of position n
    const float NEG_INF = __int_as_float(0xff800000);

    // Q for 2 positions
    ulonglong2 Q0[PPG], Q1[PPG];
    #pragma unroll
    for (int p = 0; p < PPG; ++p) {
        const float* qr = q + base + (n + p) * HD;
        Q0[p] = *(const ulonglong2*)(qr + c0);
        Q1[p] = *(const ulonglong2*)(qr + c1);
    }

    // init scores from precomputed (q.se)/8 + pb  (broadcast LDG.128)
    float s[PPG][NJ];
    #pragma unroll
    for (int p = 0; p < PPG; ++p) {
        const float4* pp = (const float4*)(g_pre + (bh * NQ + n + p) * NJ);
        #pragma unroll
        for (int t4 = 0; t4 < 5; ++t4) {
            float4 f = pp[t4];
            s[p][t4 * 4 + 0] = f.x;
            s[p][t4 * 4 + 1] = f.y;
            s[p][t4 * 4 + 2] = f.z;
            s[p][t4 * 4 + 3] = f.w;
        }
    }

    // ---- pass 1: band rows from smem, each k row shared by the pair ----
    #pragma unroll
    for (int ei = 0; ei < NE; ++ei) {
        const int e = erow(ei);
        const float* kr = sk + (liBase - e) * HD;
        const ulonglong2 K0 = *(const ulonglong2*)(kr + c0);
        const ulonglong2 K1 = *(const ulonglong2*)(kr + c1);
        #pragma unroll
        for (int p = 0; p < PPG; ++p) {
            const int j = jof(e + p);      // compile-time
            if (j >= 0) {
                float t = bfly8(dot8(Q0[p], Q1[p], K0, K1));
                s[p][j] = ((n + p) >= (e + p)) ? fmaf(t, 0.125f, s[p][j]) : NEG_INF;
            }
        }
    }

    // ---- far offsets from global (clamped loads, uniform shuffles) ----
    #pragma unroll
    for (int jf = 0; jf < 3; ++jf) {
        const int d = (jf == 0) ? 256 : ((jf == 1) ? 512 : 1024);
        const int j = 17 + jf;
        #pragma unroll
        for (int p = 0; p < PPG; ++p) {
            const bool valid = (n + p) >= d;
            const int idx = valid ? (n + p - d) : 0;
            const float* kr = k + base + idx * HD;
            const ulonglong2 K0 = *(const ulonglong2*)(kr + c0);
            const ulonglong2 K1 = *(const ulonglong2*)(kr + c1);
            float t = bfly8(dot8(Q0[p], Q1[p], K0, K1));
            s[p][j] = valid ? fmaf(t, 0.125f, s[p][j]) : NEG_INF;
        }
    }

    // ---- softmax (unnormalized weights; normalize at store) ----
    float inv[PPG];
    #pragma unroll
    for (int p = 0; p < PPG; ++p) {
        float m = s[p][0];
        #pragma unroll
        for (int j = 1; j < NJ; ++j) m = fmaxf(m, s[p][j]);
        if ((n + p) == 0) m = 0.f;
        float den = 0.f;
        #pragma unroll
        for (int j = 0; j < NJ; ++j) {
            s[p][j] = __expf(s[p][j] - m);
            den += s[p][j];
        }
        inv[p] = __frcp_rn(fmaxf(den, 1e-30f));
    }

    // ---- pass 2: weighted V with the same row reuse ----
    ulonglong2 A0[PPG], A1[PPG];
    #pragma unroll
    for (int p = 0; p < PPG; ++p) {
        A0[p].x = A0[p].y = A1[p].x = A1[p].y = 0ull;
    }

    #pragma unroll
    for (int ei = 0; ei < NE; ++ei) {
        const int e = erow(ei);
        const float* vr = sv + (liBase - e) * HD;
        const ulonglong2 V0 = *(const ulonglong2*)(vr + c0);
        const ulonglong2 V1 = *(const ulonglong2*)(vr + c1);
        #pragma unroll
        for (int p = 0; p < PPG; ++p) {
            const int j = jof(e + p);
            if (j >= 0) {
                const float w = s[p][j];   // masked positions carry w=0
                const ull w2 = pk2(w, w);
                A0[p].x = f2fma(w2, V0.x, A0[p].x);
                A0[p].y = f2fma(w2, V0.y, A0[p].y);
                A1[p].x = f2fma(w2, V1.x, A1[p].x);
                A1[p].y = f2fma(w2, V1.y, A1[p].y);
            }
        }
    }

    #pragma unroll
    for (int jf = 0; jf < 3; ++jf) {
        const int d = (jf == 0) ? 256 : ((jf == 1) ? 512 : 1024);
        const int j = 17 + jf;
        #pragma unroll
        for (int p = 0; p < PPG; ++p) {
            const bool valid = (n + p) >= d;
            const int idx = valid ? (n + p - d) : 0;
            const float* vr = v + base + idx * HD;
            const ulonglong2 V0 = *(const ulonglong2*)(vr + c0);
            const ulonglong2 V1 = *(const ulonglong2*)(vr + c1);
            const float w = valid ? s[p][j] : 0.f;
            const ull w2 = pk2(w, w);
            A0[p].x = f2fma(w2, V0.x, A0[p].x);
            A0[p].y = f2fma(w2, V0.y, A0[p].y);
            A1[p].x = f2fma(w2, V1.x, A1[p].x);
            A1[p].y = f2fma(w2, V1.y, A1[p].y);
        }
    }

    // ---- normalize + store ----
    #pragma unroll
    for (int p = 0; p < PPG; ++p) {
        const ull iv2 = pk2(inv[p], inv[p]);
        ulonglong2 R0, R1;
        R0.x = f2mul(A0[p].x, iv2);
        R0.y = f2mul(A0[p].y, iv2);
        R1.x = f2mul(A1[p].x, iv2);
        R1.y = f2mul(A1[p].y, iv2);
        float* outr = out + base + (n + p) * HD;
        *(ulonglong2*)(outr + c0) = R0;
        *(ulonglong2*)(outr + c1) = R1;
    }
}

extern "C" void kernel_launch(void* const* d_in, const int* in_sizes, int n_in,
                              void* d_out, int out_size)
{
    const float* q  = (const float*)d_in[0];
    const float* k  = (const float*)d_in[1];
    const float* v  = (const float*)d_in[2];
    const float* pb = (const float*)d_in[3];
    const float* se = (const float*)d_in[4];
    float* out = (float*)d_out;

    cudaFuncSetAttribute(dsqg_pre_kernel,
                         cudaFuncAttributeMaxDynamicSharedMemorySize, PRE_SMEM_BYTES);
    cudaFuncSetAttribute(dsqg_attn_kernel,
                         cudaFuncAttributeMaxDynamicSharedMemorySize, SMEM_BYTES);

    dim3 gridA(NQ / PRE_TILE, BQ * HQ);
    dsqg_pre_kernel<<<gridA, 256, PRE_SMEM_BYTES>>>(q, pb, se);

    dim3 gridB(NQ / TILE, BQ * HQ);
    dsqg_attn_kernel<<<gridB, 1024, SMEM_BYTES>>>(q, k, v, out);
}